// round 2
// baseline (speedup 1.0000x reference)
#include <cuda_runtime.h>

#define NM 128
#define NM3 (NM * NM * NM)
#define NC 16
#define NPTS 100000
#define INV_SPACING 10.0f

// Scratch: mesh transposed to (x,y,z,c) layout, viewed as float4 chunks of 4 channels.
// (x*128+y)*128+z cell index; cell*4 + cch indexes channels [4*cch, 4*cch+4).
__device__ float4 g_scratch[NM3 * (NC / 4)];

// ---------------------------------------------------------------------------
// Kernel 1: transpose (c, cell) -> (cell, c)
// One thread per cell. Reads are warp-coalesced (32 consecutive cells * 4B =
// 128B per channel). Writes are 4x float4 per thread covering a contiguous
// 2KB span per warp.
// ---------------------------------------------------------------------------
__global__ void mesh_transpose_kernel(const float* __restrict__ in) {
    int cell = blockIdx.x * blockDim.x + threadIdx.x;
    if (cell >= NM3) return;

    float v[NC];
#pragma unroll
    for (int c = 0; c < NC; c++) {
        v[c] = __ldg(in + (size_t)c * NM3 + cell);
    }

    float4* o = g_scratch + (size_t)cell * 4;
    o[0] = make_float4(v[0],  v[1],  v[2],  v[3]);
    o[1] = make_float4(v[4],  v[5],  v[6],  v[7]);
    o[2] = make_float4(v[8],  v[9],  v[10], v[11]);
    o[3] = make_float4(v[12], v[13], v[14], v[15]);
}

// ---------------------------------------------------------------------------
// Kernel 2: TSC interpolation.
// 4 threads per point; thread owns 4 channels (one float4 chunk).
// 27 fully-unrolled independent LDG.128 per thread -> high MLP.
// ---------------------------------------------------------------------------
__global__ void interp_kernel(const float* __restrict__ points,
                              float4* __restrict__ out) {
    int t = blockIdx.x * blockDim.x + threadIdx.x;
    int p = t >> 2;
    int cch = t & 3;
    if (p >= NPTS) return;

    float px = points[p * 3 + 0] * INV_SPACING;
    float py = points[p * 3 + 1] * INV_SPACING;
    float pz = points[p * 3 + 2] * INV_SPACING;

    float rx = rintf(px), ry = rintf(py), rz = rintf(pz);
    float dx = px - rx, dy = py - ry, dz = pz - rz;
    int ix = (int)rx, iy = (int)ry, iz = (int)rz;

    // TSC weights: w_m = (2d-1)^2/8, w_0 = 0.75 - d^2, w_p = (2d+1)^2/8
    float wx[3], wy[3], wz[3];
    {
        float a;
        a = 2.0f * dx - 1.0f; wx[0] = a * a * 0.125f;
        wx[1] = 0.75f - dx * dx;
        a = 2.0f * dx + 1.0f; wx[2] = a * a * 0.125f;

        a = 2.0f * dy - 1.0f; wy[0] = a * a * 0.125f;
        wy[1] = 0.75f - dy * dy;
        a = 2.0f * dy + 1.0f; wy[2] = a * a * 0.125f;

        a = 2.0f * dz - 1.0f; wz[0] = a * a * 0.125f;
        wz[1] = 0.75f - dz * dz;
        a = 2.0f * dz + 1.0f; wz[2] = a * a * 0.125f;
    }

    // Periodic wrap: ix in [0, 128]; (ix + off + 128) & 127 matches jax %
    int xs[3], ys[3], zs[3];
    xs[0] = (ix + 127) & (NM - 1); xs[1] = ix & (NM - 1); xs[2] = (ix + 129) & (NM - 1);
    ys[0] = (iy + 127) & (NM - 1); ys[1] = iy & (NM - 1); ys[2] = (iy + 129) & (NM - 1);
    zs[0] = (iz + 127) & (NM - 1); zs[1] = iz & (NM - 1); zs[2] = (iz + 129) & (NM - 1);

    float4 acc = make_float4(0.0f, 0.0f, 0.0f, 0.0f);

#pragma unroll
    for (int ox = 0; ox < 3; ox++) {
#pragma unroll
        for (int oy = 0; oy < 3; oy++) {
            float wxy = wx[ox] * wy[oy];
            int rowbase = (xs[ox] * NM + ys[oy]) * NM;
#pragma unroll
            for (int oz = 0; oz < 3; oz++) {
                float w = wxy * wz[oz];
                float4 v = g_scratch[(size_t)(rowbase + zs[oz]) * 4 + cch];
                acc.x += w * v.x;
                acc.y += w * v.y;
                acc.z += w * v.z;
                acc.w += w * v.w;
            }
        }
    }

    out[(size_t)p * 4 + cch] = acc;
}

extern "C" void kernel_launch(void* const* d_in, const int* in_sizes, int n_in,
                              void* d_out, int out_size) {
    const float* mesh = (const float*)d_in[0];    // (16, 128, 128, 128) f32
    const float* points = (const float*)d_in[1];  // (100000, 3) f32
    float4* out = (float4*)d_out;                 // (100000, 16) f32

    {
        int threads = 256;
        int blocks = (NM3 + threads - 1) / threads;
        mesh_transpose_kernel<<<blocks, threads>>>(mesh);
    }
    {
        int total = NPTS * 4;
        int threads = 256;
        int blocks = (total + threads - 1) / threads;
        interp_kernel<<<blocks, threads>>>(points, out);
    }
}

// round 5
// speedup vs baseline: 1.1439x; 1.1439x over previous
#include <cuda_runtime.h>
#include <cuda_fp16.h>
#include <string.h>

#define NM 128
#define NM3 (NM * NM * NM)
#define NC 16
#define NPTS 100000
#define INV_SPACING 10.0f

// Scratch: mesh transposed to (x,y,z,c) fp16 layout.
// One cell = 16 halfs = 32 bytes = 2 uint4. Index: cell*2 + half_sel.
__device__ uint4 g_scratch[NM3 * 2];

static __device__ __forceinline__ unsigned h2u(__half2 h) {
    unsigned u; memcpy(&u, &h, 4); return u;
}
static __device__ __forceinline__ __half2 u2h(unsigned u) {
    __half2 h; memcpy(&h, &u, 4); return h;
}

// ---------------------------------------------------------------------------
// Kernel 1: transpose (c, cell)f32 -> (cell, c)f16
// One thread per 4 consecutive z-cells. Reads: 16 coalesced LDG.128.
// Writes: 8 STG.128 covering 128B contiguous per thread.
// ---------------------------------------------------------------------------
__global__ void mesh_transpose_f16_kernel(const float* __restrict__ in) {
    int q = blockIdx.x * blockDim.x + threadIdx.x;   // quad-cell index
    if (q >= NM3 / 4) return;
    int cell0 = q * 4;

    float4 v[NC];
#pragma unroll
    for (int c = 0; c < NC; c++) {
        v[c] = __ldg((const float4*)(in + (size_t)c * NM3 + cell0));
    }

    uint4* o = g_scratch + (size_t)cell0 * 2;
#pragma unroll
    for (int z = 0; z < 4; z++) {
        // channel values for this cell
        float f[NC];
#pragma unroll
        for (int c = 0; c < NC; c++) {
            f[c] = (z == 0) ? v[c].x : (z == 1) ? v[c].y : (z == 2) ? v[c].z : v[c].w;
        }
        uint4 lo, hi;
        lo.x = h2u(__floats2half2_rn(f[0],  f[1]));
        lo.y = h2u(__floats2half2_rn(f[2],  f[3]));
        lo.z = h2u(__floats2half2_rn(f[4],  f[5]));
        lo.w = h2u(__floats2half2_rn(f[6],  f[7]));
        hi.x = h2u(__floats2half2_rn(f[8],  f[9]));
        hi.y = h2u(__floats2half2_rn(f[10], f[11]));
        hi.z = h2u(__floats2half2_rn(f[12], f[13]));
        hi.w = h2u(__floats2half2_rn(f[14], f[15]));
        o[z * 2 + 0] = lo;
        o[z * 2 + 1] = hi;
    }
}

// ---------------------------------------------------------------------------
// Kernel 2: TSC interpolation on fp16 scratch.
// 2 threads per point; thread owns 8 channels (one uint4 = 16B per tap).
// 27 fully-unrolled independent LDG.128 per thread -> high MLP.
// fp32 weights + fp32 accumulation.
// ---------------------------------------------------------------------------
__global__ void interp_f16_kernel(const float* __restrict__ points,
                                  float4* __restrict__ out) {
    int t = blockIdx.x * blockDim.x + threadIdx.x;
    int p = t >> 1;
    int hsel = t & 1;   // channels [8*hsel, 8*hsel+8)
    if (p >= NPTS) return;

    float px = points[p * 3 + 0] * INV_SPACING;
    float py = points[p * 3 + 1] * INV_SPACING;
    float pz = points[p * 3 + 2] * INV_SPACING;

    float rx = rintf(px), ry = rintf(py), rz = rintf(pz);
    float dx = px - rx, dy = py - ry, dz = pz - rz;
    int ix = (int)rx, iy = (int)ry, iz = (int)rz;

    float wx[3], wy[3], wz[3];
    {
        float a;
        a = 2.0f * dx - 1.0f; wx[0] = a * a * 0.125f;
        wx[1] = 0.75f - dx * dx;
        a = 2.0f * dx + 1.0f; wx[2] = a * a * 0.125f;

        a = 2.0f * dy - 1.0f; wy[0] = a * a * 0.125f;
        wy[1] = 0.75f - dy * dy;
        a = 2.0f * dy + 1.0f; wy[2] = a * a * 0.125f;

        a = 2.0f * dz - 1.0f; wz[0] = a * a * 0.125f;
        wz[1] = 0.75f - dz * dz;
        a = 2.0f * dz + 1.0f; wz[2] = a * a * 0.125f;
    }

    int xs[3], ys[3], zs[3];
    xs[0] = (ix + 127) & (NM - 1); xs[1] = ix & (NM - 1); xs[2] = (ix + 129) & (NM - 1);
    ys[0] = (iy + 127) & (NM - 1); ys[1] = iy & (NM - 1); ys[2] = (iy + 129) & (NM - 1);
    zs[0] = (iz + 127) & (NM - 1); zs[1] = iz & (NM - 1); zs[2] = (iz + 129) & (NM - 1);

    float a0 = 0.f, a1 = 0.f, a2 = 0.f, a3 = 0.f,
          a4 = 0.f, a5 = 0.f, a6 = 0.f, a7 = 0.f;

#pragma unroll
    for (int ox = 0; ox < 3; ox++) {
#pragma unroll
        for (int oy = 0; oy < 3; oy++) {
            float wxy = wx[ox] * wy[oy];
            int rowbase = (xs[ox] * NM + ys[oy]) * NM;
#pragma unroll
            for (int oz = 0; oz < 3; oz++) {
                float w = wxy * wz[oz];
                uint4 raw = g_scratch[(size_t)(rowbase + zs[oz]) * 2 + hsel];
                float2 f0 = __half22float2(u2h(raw.x));
                float2 f1 = __half22float2(u2h(raw.y));
                float2 f2 = __half22float2(u2h(raw.z));
                float2 f3 = __half22float2(u2h(raw.w));
                a0 += w * f0.x; a1 += w * f0.y;
                a2 += w * f1.x; a3 += w * f1.y;
                a4 += w * f2.x; a5 += w * f2.y;
                a6 += w * f3.x; a7 += w * f3.y;
            }
        }
    }

    float4* o = out + (size_t)p * 4 + hsel * 2;
    o[0] = make_float4(a0, a1, a2, a3);
    o[1] = make_float4(a4, a5, a6, a7);
}

extern "C" void kernel_launch(void* const* d_in, const int* in_sizes, int n_in,
                              void* d_out, int out_size) {
    const float* mesh = (const float*)d_in[0];    // (16, 128, 128, 128) f32
    const float* points = (const float*)d_in[1];  // (100000, 3) f32
    float4* out = (float4*)d_out;                 // (100000, 16) f32

    {
        int threads = 256;
        int blocks = (NM3 / 4 + threads - 1) / threads;
        mesh_transpose_f16_kernel<<<blocks, threads>>>(mesh);
    }
    {
        int total = NPTS * 2;
        int threads = 256;
        int blocks = (total + threads - 1) / threads;
        interp_f16_kernel<<<blocks, threads>>>(points, out);
    }
}

// round 6
// speedup vs baseline: 1.3562x; 1.1856x over previous
#include <cuda_runtime.h>
#include <cuda_fp16.h>
#include <string.h>

#define NM 128
#define NM3 (NM * NM * NM)
#define NC 16
#define NPTS 100000
#define INV_SPACING 10.0f

// Scratch: mesh transposed to (x,y,z,c) fp16 layout.
// One cell = 16 halfs = 32 bytes = 2 uint4. Index: cell*2 + half_sel.
__device__ uint4 g_scratch[NM3 * 2];

static __device__ __forceinline__ unsigned h2u(__half2 h) {
    unsigned u; memcpy(&u, &h, 4); return u;
}
static __device__ __forceinline__ __half2 u2h(unsigned u) {
    __half2 h; memcpy(&h, &u, 4); return h;
}

// ---------------------------------------------------------------------------
// Kernel 1: transpose (c, cell)f32 -> (cell, c)f16
// One thread per 4 consecutive z-cells.
// Reads: 16 coalesced LDG.128 with .cs (evict-first) hint — read-once stream
// must NOT evict the scratch lines we are writing into L2.
// Writes: 8 STG.128 (default write-back -> stays dirty in L2, 67MB < 126MB).
// ---------------------------------------------------------------------------
__global__ void mesh_transpose_f16_kernel(const float* __restrict__ in) {
    int q = blockIdx.x * blockDim.x + threadIdx.x;   // quad-cell index
    if (q >= NM3 / 4) return;
    int cell0 = q * 4;

    float4 v[NC];
#pragma unroll
    for (int c = 0; c < NC; c++) {
        v[c] = __ldcs((const float4*)(in + (size_t)c * NM3 + cell0));
    }

    uint4* o = g_scratch + (size_t)cell0 * 2;
#pragma unroll
    for (int z = 0; z < 4; z++) {
        // channel values for this cell
        float f[NC];
#pragma unroll
        for (int c = 0; c < NC; c++) {
            f[c] = (z == 0) ? v[c].x : (z == 1) ? v[c].y : (z == 2) ? v[c].z : v[c].w;
        }
        uint4 lo, hi;
        lo.x = h2u(__floats2half2_rn(f[0],  f[1]));
        lo.y = h2u(__floats2half2_rn(f[2],  f[3]));
        lo.z = h2u(__floats2half2_rn(f[4],  f[5]));
        lo.w = h2u(__floats2half2_rn(f[6],  f[7]));
        hi.x = h2u(__floats2half2_rn(f[8],  f[9]));
        hi.y = h2u(__floats2half2_rn(f[10], f[11]));
        hi.z = h2u(__floats2half2_rn(f[12], f[13]));
        hi.w = h2u(__floats2half2_rn(f[14], f[15]));
        o[z * 2 + 0] = lo;
        o[z * 2 + 1] = hi;
    }
}

// ---------------------------------------------------------------------------
// Kernel 2: TSC interpolation on fp16 scratch (expected L2-resident).
// 2 threads per point; thread owns 8 channels (one uint4 = 16B per tap).
// 27 fully-unrolled independent LDG.128 per thread -> high MLP.
// fp32 weights + fp32 accumulation. Output stored with .cs (never re-read).
// ---------------------------------------------------------------------------
__global__ void interp_f16_kernel(const float* __restrict__ points,
                                  float4* __restrict__ out) {
    int t = blockIdx.x * blockDim.x + threadIdx.x;
    int p = t >> 1;
    int hsel = t & 1;   // channels [8*hsel, 8*hsel+8)
    if (p >= NPTS) return;

    float px = points[p * 3 + 0] * INV_SPACING;
    float py = points[p * 3 + 1] * INV_SPACING;
    float pz = points[p * 3 + 2] * INV_SPACING;

    float rx = rintf(px), ry = rintf(py), rz = rintf(pz);
    float dx = px - rx, dy = py - ry, dz = pz - rz;
    int ix = (int)rx, iy = (int)ry, iz = (int)rz;

    float wx[3], wy[3], wz[3];
    {
        float a;
        a = 2.0f * dx - 1.0f; wx[0] = a * a * 0.125f;
        wx[1] = 0.75f - dx * dx;
        a = 2.0f * dx + 1.0f; wx[2] = a * a * 0.125f;

        a = 2.0f * dy - 1.0f; wy[0] = a * a * 0.125f;
        wy[1] = 0.75f - dy * dy;
        a = 2.0f * dy + 1.0f; wy[2] = a * a * 0.125f;

        a = 2.0f * dz - 1.0f; wz[0] = a * a * 0.125f;
        wz[1] = 0.75f - dz * dz;
        a = 2.0f * dz + 1.0f; wz[2] = a * a * 0.125f;
    }

    int xs[3], ys[3], zs[3];
    xs[0] = (ix + 127) & (NM - 1); xs[1] = ix & (NM - 1); xs[2] = (ix + 129) & (NM - 1);
    ys[0] = (iy + 127) & (NM - 1); ys[1] = iy & (NM - 1); ys[2] = (iy + 129) & (NM - 1);
    zs[0] = (iz + 127) & (NM - 1); zs[1] = iz & (NM - 1); zs[2] = (iz + 129) & (NM - 1);

    float a0 = 0.f, a1 = 0.f, a2 = 0.f, a3 = 0.f,
          a4 = 0.f, a5 = 0.f, a6 = 0.f, a7 = 0.f;

#pragma unroll
    for (int ox = 0; ox < 3; ox++) {
#pragma unroll
        for (int oy = 0; oy < 3; oy++) {
            float wxy = wx[ox] * wy[oy];
            int rowbase = (xs[ox] * NM + ys[oy]) * NM;
#pragma unroll
            for (int oz = 0; oz < 3; oz++) {
                float w = wxy * wz[oz];
                uint4 raw = g_scratch[(size_t)(rowbase + zs[oz]) * 2 + hsel];
                float2 f0 = __half22float2(u2h(raw.x));
                float2 f1 = __half22float2(u2h(raw.y));
                float2 f2 = __half22float2(u2h(raw.z));
                float2 f3 = __half22float2(u2h(raw.w));
                a0 += w * f0.x; a1 += w * f0.y;
                a2 += w * f1.x; a3 += w * f1.y;
                a4 += w * f2.x; a5 += w * f2.y;
                a6 += w * f3.x; a7 += w * f3.y;
            }
        }
    }

    float4* o = out + (size_t)p * 4 + hsel * 2;
    __stcs(o + 0, make_float4(a0, a1, a2, a3));
    __stcs(o + 1, make_float4(a4, a5, a6, a7));
}

extern "C" void kernel_launch(void* const* d_in, const int* in_sizes, int n_in,
                              void* d_out, int out_size) {
    const float* mesh = (const float*)d_in[0];    // (16, 128, 128, 128) f32
    const float* points = (const float*)d_in[1];  // (100000, 3) f32
    float4* out = (float4*)d_out;                 // (100000, 16) f32

    {
        int threads = 256;
        int blocks = (NM3 / 4 + threads - 1) / threads;
        mesh_transpose_f16_kernel<<<blocks, threads>>>(mesh);
    }
    {
        int total = NPTS * 2;
        int threads = 256;
        int blocks = (total + threads - 1) / threads;
        interp_f16_kernel<<<blocks, threads>>>(points, out);
    }
}

// round 9
// speedup vs baseline: 1.5606x; 1.1507x over previous
#include <cuda_runtime.h>
#include <cuda_fp16.h>
#include <string.h>

#define NM 128
#define NM3 (NM * NM * NM)
#define NC 16
#define NPTS 100000
#define INV_SPACING 10.0f

// Scratch: mesh transposed to (x,y,z,c) fp16 layout.
// One cell = 16 halfs = 32 bytes = one ulonglong4 (accessed as LDG/STG.256).
__device__ ulonglong4 g_scratch[NM3];

static __device__ __forceinline__ unsigned h2u(__half2 h) {
    unsigned u; memcpy(&u, &h, 4); return u;
}
static __device__ __forceinline__ __half2 u2h(unsigned u) {
    __half2 h; memcpy(&h, &u, 4); return h;
}
static __device__ __forceinline__ unsigned long long pack64(unsigned lo, unsigned hi) {
    return (unsigned long long)lo | ((unsigned long long)hi << 32);
}

// --- 256-bit L2-pinned scratch access (evict_last requires .v4.b64) ---------
static __device__ __forceinline__ void st_cell_evict_last(ulonglong4* p, ulonglong4 v) {
    asm volatile("st.global.L2::evict_last.v4.b64 [%0], {%1,%2,%3,%4};"
                 :: "l"(p), "l"(v.x), "l"(v.y), "l"(v.z), "l"(v.w) : "memory");
}
static __device__ __forceinline__ ulonglong4 ld_cell_evict_last(const ulonglong4* p) {
    ulonglong4 r;
    asm("ld.global.nc.L2::evict_last.v4.b64 {%0,%1,%2,%3}, [%4];"
        : "=l"(r.x), "=l"(r.y), "=l"(r.z), "=l"(r.w) : "l"(p));
    return r;
}

// ---------------------------------------------------------------------------
// Kernel 1: transpose (c, cell)f32 -> (cell, c)f16
// One thread per 4 consecutive z-cells.
// Reads: 16 coalesced LDG.128 with .cs streaming hint (read-once).
// Writes: 4 STG.256 with L2::evict_last (pin the 67MB scratch in 126MB L2).
// ---------------------------------------------------------------------------
__global__ void mesh_transpose_f16_kernel(const float* __restrict__ in) {
    int q = blockIdx.x * blockDim.x + threadIdx.x;   // quad-cell index
    if (q >= NM3 / 4) return;
    int cell0 = q * 4;

    float4 v[NC];
#pragma unroll
    for (int c = 0; c < NC; c++) {
        v[c] = __ldcs((const float4*)(in + (size_t)c * NM3 + cell0));
    }

#pragma unroll
    for (int z = 0; z < 4; z++) {
        float f[NC];
#pragma unroll
        for (int c = 0; c < NC; c++) {
            f[c] = (z == 0) ? v[c].x : (z == 1) ? v[c].y : (z == 2) ? v[c].z : v[c].w;
        }
        unsigned u0 = h2u(__floats2half2_rn(f[0],  f[1]));
        unsigned u1 = h2u(__floats2half2_rn(f[2],  f[3]));
        unsigned u2 = h2u(__floats2half2_rn(f[4],  f[5]));
        unsigned u3 = h2u(__floats2half2_rn(f[6],  f[7]));
        unsigned u4 = h2u(__floats2half2_rn(f[8],  f[9]));
        unsigned u5 = h2u(__floats2half2_rn(f[10], f[11]));
        unsigned u6 = h2u(__floats2half2_rn(f[12], f[13]));
        unsigned u7 = h2u(__floats2half2_rn(f[14], f[15]));
        ulonglong4 cell;
        cell.x = pack64(u0, u1);
        cell.y = pack64(u2, u3);
        cell.z = pack64(u4, u5);
        cell.w = pack64(u6, u7);
        st_cell_evict_last(&g_scratch[cell0 + z], cell);
    }
}

// ---------------------------------------------------------------------------
// Kernel 2: TSC interpolation on (ideally L2-resident) fp16 scratch.
// ONE thread per point; each stencil tap is a single 32B LDG.256 (whole cell,
// all 16 channels). 27 fully-unrolled independent loads -> high MLP.
// fp32 weights + fp32 accumulation. Output: 64B contiguous via 4x STG.128.cs.
// ---------------------------------------------------------------------------
__global__ void interp_f16_kernel(const float* __restrict__ points,
                                  float4* __restrict__ out) {
    int p = blockIdx.x * blockDim.x + threadIdx.x;
    if (p >= NPTS) return;

    float px = points[p * 3 + 0] * INV_SPACING;
    float py = points[p * 3 + 1] * INV_SPACING;
    float pz = points[p * 3 + 2] * INV_SPACING;

    float rx = rintf(px), ry = rintf(py), rz = rintf(pz);
    float dx = px - rx, dy = py - ry, dz = pz - rz;
    int ix = (int)rx, iy = (int)ry, iz = (int)rz;

    float wx[3], wy[3], wz[3];
    {
        float a;
        a = 2.0f * dx - 1.0f; wx[0] = a * a * 0.125f;
        wx[1] = 0.75f - dx * dx;
        a = 2.0f * dx + 1.0f; wx[2] = a * a * 0.125f;

        a = 2.0f * dy - 1.0f; wy[0] = a * a * 0.125f;
        wy[1] = 0.75f - dy * dy;
        a = 2.0f * dy + 1.0f; wy[2] = a * a * 0.125f;

        a = 2.0f * dz - 1.0f; wz[0] = a * a * 0.125f;
        wz[1] = 0.75f - dz * dz;
        a = 2.0f * dz + 1.0f; wz[2] = a * a * 0.125f;
    }

    int xs[3], ys[3], zs[3];
    xs[0] = (ix + 127) & (NM - 1); xs[1] = ix & (NM - 1); xs[2] = (ix + 129) & (NM - 1);
    ys[0] = (iy + 127) & (NM - 1); ys[1] = iy & (NM - 1); ys[2] = (iy + 129) & (NM - 1);
    zs[0] = (iz + 127) & (NM - 1); zs[1] = iz & (NM - 1); zs[2] = (iz + 129) & (NM - 1);

    float acc[NC];
#pragma unroll
    for (int c = 0; c < NC; c++) acc[c] = 0.0f;

#pragma unroll
    for (int ox = 0; ox < 3; ox++) {
#pragma unroll
        for (int oy = 0; oy < 3; oy++) {
            float wxy = wx[ox] * wy[oy];
            int rowbase = (xs[ox] * NM + ys[oy]) * NM;
#pragma unroll
            for (int oz = 0; oz < 3; oz++) {
                float w = wxy * wz[oz];
                ulonglong4 raw = ld_cell_evict_last(&g_scratch[rowbase + zs[oz]]);
                unsigned long long qd[4] = {raw.x, raw.y, raw.z, raw.w};
#pragma unroll
                for (int j = 0; j < 4; j++) {
                    unsigned lo = (unsigned)qd[j];
                    unsigned hi = (unsigned)(qd[j] >> 32);
                    float2 f0 = __half22float2(u2h(lo));
                    float2 f1 = __half22float2(u2h(hi));
                    acc[j * 4 + 0] += w * f0.x;
                    acc[j * 4 + 1] += w * f0.y;
                    acc[j * 4 + 2] += w * f1.x;
                    acc[j * 4 + 3] += w * f1.y;
                }
            }
        }
    }

    float4* o = out + (size_t)p * 4;
    __stcs(o + 0, make_float4(acc[0],  acc[1],  acc[2],  acc[3]));
    __stcs(o + 1, make_float4(acc[4],  acc[5],  acc[6],  acc[7]));
    __stcs(o + 2, make_float4(acc[8],  acc[9],  acc[10], acc[11]));
    __stcs(o + 3, make_float4(acc[12], acc[13], acc[14], acc[15]));
}

extern "C" void kernel_launch(void* const* d_in, const int* in_sizes, int n_in,
                              void* d_out, int out_size) {
    const float* mesh = (const float*)d_in[0];    // (16, 128, 128, 128) f32
    const float* points = (const float*)d_in[1];  // (100000, 3) f32
    float4* out = (float4*)d_out;                 // (100000, 16) f32

    {
        int threads = 256;
        int blocks = (NM3 / 4 + threads - 1) / threads;
        mesh_transpose_f16_kernel<<<blocks, threads>>>(mesh);
    }
    {
        int threads = 256;
        int blocks = (NPTS + threads - 1) / threads;
        interp_f16_kernel<<<blocks, threads>>>(points, out);
    }
}